// round 3
// baseline (speedup 1.0000x reference)
#include <cuda_runtime.h>
#include <cstdint>

typedef unsigned long long u64;

#define BATCH 32
#define HID   64
#define CHUNK 2048
#define CMASK (CHUNK-1)
#define LOGC  11

__device__ __forceinline__ u64 fma2(u64 a, u64 b, u64 c){
    u64 d; asm("fma.rn.f32x2 %0, %1, %2, %3;" : "=l"(d) : "l"(a), "l"(b), "l"(c)); return d;
}
__device__ __forceinline__ u64 add2(u64 a, u64 b){
    u64 d; asm("add.rn.f32x2 %0, %1, %2;" : "=l"(d) : "l"(a), "l"(b)); return d;
}
__device__ __forceinline__ float hsum2(u64 a){
    float lo, hi; asm("mov.b64 {%0,%1}, %2;" : "=f"(lo), "=f"(hi) : "l"(a)); return lo + hi;
}
// sigmoid via MUFU ex2+rcp chain: rel err ~1e-7
__device__ __forceinline__ float fsig(float v){
    float e = __expf(-v);
    return __fdividef(1.0f, 1.0f + e);
}
// tanh(v) = 1 - 2/(exp(2v)+1); saturates correctly at +/-inf
__device__ __forceinline__ float ftanh(float v){
    float e = __expf(2.0f * v);
    return 1.0f - __fdividef(2.0f, e + 1.0f);
}
__device__ __forceinline__ void gbar(int id){
    asm volatile("bar.sync %0, 128;" :: "r"(id) : "memory");
}

// 2 independent batch rows per CTA (group = tid/128). Each group: 128 threads,
// pair (2i, 2i+1) owns hidden unit i. Lane p=0: full 64-dot for r; p=1: full
// 64-dot for z; both: half 32-dot for n (combined via shfl_xor 1).
// 2 warps per SMSP (one from each group) hide each other's latency; groups
// sync on separate named barriers so they stay decoupled.
__global__ void __launch_bounds__(256, 1)
gru_kernel(const float* __restrict__ x, const float* __restrict__ w_ih,
           const float* __restrict__ w_hh, const float* __restrict__ b_ih,
           const float* __restrict__ b_hh, float* __restrict__ states, int T)
{
    __shared__ __align__(16) float hbuf[2][2][HID];     // [group][buf][unit]
    __shared__ __align__(16) float xs[2][2][CHUNK];     // [group][buf][t]

    const int tid = threadIdx.x;
    const int g   = tid >> 7;          // group (0/1)
    const int wt  = tid & 127;         // thread-in-group
    const int b   = blockIdx.x * 2 + g;
    const int i   = wt >> 1;
    const int p   = wt & 1;
    const int ia  = i + 64 * p;        // gate-a row: r (p=0) or z (p=1)
    const int in_ = 128 + i;           // n-gate row
    const int bar = 1 + g;

    // --- weights into registers (packed f32x2) ---
    u64 wa[32];
    {
        const u64* was = (const u64*)(w_hh + ia * 64);
        #pragma unroll
        for (int q = 0; q < 32; q++) wa[q] = was[q];
    }
    u64 wn[16];
    {
        const u64* wns = (const u64*)(w_hh + in_ * 64 + 32 * p);
        #pragma unroll
        for (int q = 0; q < 16; q++) wn[q] = wns[q];
    }

    const float bhh_a = b_hh[ia], bih_a = b_ih[ia], wih_a = w_ih[ia];
    const float bhh_n = b_hh[in_], bih_n = b_ih[in_], wih_n = w_ih[in_];
    const float ca = bhh_a + bih_a;

    const float* xrow = x + (size_t)b * T;

    if (wt < HID) hbuf[g][0][wt] = 0.0f;
    {
        const float4* src = (const float4*)xrow;
        float4* dst = (float4*)xs[g][0];
        #pragma unroll
        for (int q = 0; q < CHUNK / 4 / 128; q++) dst[wt + q * 128] = src[wt + q * 128];
    }
    gbar(bar);

    float* sout = states + ((size_t)b * T) * HID + i;

    for (int t = 0; t < T; ++t) {
        // prefetch next x chunk (group-uniform branch)
        if ((t & CMASK) == 0) {
            int nc = (t >> LOGC) + 1;
            if (nc * CHUNK < T) {
                const float4* src = (const float4*)(xrow + (size_t)nc * CHUNK);
                float4* dst = (float4*)xs[g][nc & 1];
                #pragma unroll
                for (int q = 0; q < CHUNK / 4 / 128; q++) dst[wt + q * 128] = src[wt + q * 128];
            }
        }

        const int cur = t & 1;
        const float* hc = hbuf[g][cur];
        const float xt = xs[g][(t >> LOGC) & 1][t & CMASK];
        const float hprev = hc[i];
        const float xa = fmaf(xt, wih_a, ca);
        const float xn = fmaf(xt, wih_n, bih_n);

        // full 64-dot for gate a (r or z): 8 accumulators, depth 4
        u64 a0 = 0, a1 = 0, a2 = 0, a3 = 0, a4 = 0, a5 = 0, a6 = 0, a7 = 0;
        const ulonglong2* hs = (const ulonglong2*)hc;
        #pragma unroll
        for (int q = 0; q < 4; q++) {
            ulonglong2 h0 = hs[4 * q];
            ulonglong2 h1 = hs[4 * q + 1];
            ulonglong2 h2 = hs[4 * q + 2];
            ulonglong2 h3 = hs[4 * q + 3];
            a0 = fma2(h0.x, wa[8 * q],     a0);
            a1 = fma2(h0.y, wa[8 * q + 1], a1);
            a2 = fma2(h1.x, wa[8 * q + 2], a2);
            a3 = fma2(h1.y, wa[8 * q + 3], a3);
            a4 = fma2(h2.x, wa[8 * q + 4], a4);
            a5 = fma2(h2.y, wa[8 * q + 5], a5);
            a6 = fma2(h3.x, wa[8 * q + 6], a6);
            a7 = fma2(h3.y, wa[8 * q + 7], a7);
        }
        float sa = hsum2(add2(add2(add2(a0, a1), add2(a2, a3)),
                              add2(add2(a4, a5), add2(a6, a7))));
        float ga = fsig(sa + xa);   // overlaps with n-dot below

        // half 32-dot for n-gate: 4 accumulators, depth 4 (16 u64 = 32 floats)
        u64 n0 = 0, n1 = 0, n2 = 0, n3 = 0;
        const ulonglong2* hsn = (const ulonglong2*)(hc + 32 * p);
        #pragma unroll
        for (int q = 0; q < 4; q++) {
            ulonglong2 h0 = hsn[2 * q];
            ulonglong2 h1 = hsn[2 * q + 1];
            n0 = fma2(h0.x, wn[4 * q],     n0);
            n1 = fma2(h0.y, wn[4 * q + 1], n1);
            n2 = fma2(h1.x, wn[4 * q + 2], n2);
            n3 = fma2(h1.y, wn[4 * q + 3], n3);
        }
        float snp = hsum2(add2(add2(n0, n1), add2(n2, n3)));
        float sn  = snp + __shfl_xor_sync(0xffffffffu, snp, 1);
        float gb  = __shfl_xor_sync(0xffffffffu, ga, 1);
        float r = p ? gb : ga;
        float z = p ? ga : gb;
        float hn = sn + bhh_n;
        float n  = ftanh(fmaf(r, hn, xn));
        float hnew = fmaf(z, hprev - n, n);   // (1-z)*n + z*h

        if (!p) {
            hbuf[g][cur ^ 1][i] = hnew;
            sout[(size_t)t * HID] = hnew;
        }
        gbar(bar);
    }
}

// out[n] = dot(states[n,:], w_lin) + b_lin + x[n]
// Coalesced: stage a 128-row tile (128x64) through padded smem.
#define HROWS 128
#define HPAD  65
__global__ void __launch_bounds__(128, 8)
head_kernel(const float* __restrict__ st, const float* __restrict__ x,
            const float* __restrict__ wl, const float* __restrict__ bl,
            float* __restrict__ out, int BT)
{
    __shared__ float tile[HROWS * HPAD];
    __shared__ float wsh[HID];

    const int tid = threadIdx.x;
    const size_t row0 = (size_t)blockIdx.x * HROWS;

    if (tid < HID) wsh[tid] = wl[tid];

    // coalesced load of 128x64 floats, scatter into padded smem
    const float4* src = (const float4*)(st + row0 * HID);
    #pragma unroll
    for (int q = 0; q < (HROWS * HID / 4) / 128; q++) {
        int f4 = tid + q * 128;          // float4 index
        float4 v = src[f4];
        int flat = f4 * 4;
        int r = flat >> 6;
        int c = flat & 63;
        float* drow = &tile[r * HPAD + c];
        drow[0] = v.x; drow[1] = v.y; drow[2] = v.z; drow[3] = v.w;
    }
    __syncthreads();

    // one thread per row
    const float* trow = &tile[tid * HPAD];
    float acc = 0.0f;
    #pragma unroll
    for (int k = 0; k < HID; k++) acc = fmaf(trow[k], wsh[k], acc);

    size_t n = row0 + tid;
    out[n] = acc + bl[0] + x[n];
}

extern "C" void kernel_launch(void* const* d_in, const int* in_sizes, int n_in,
                              void* d_out, int out_size)
{
    const float* x     = (const float*)d_in[0];
    const float* w_ih  = (const float*)d_in[1];
    const float* w_hh  = (const float*)d_in[2];
    const float* b_ih  = (const float*)d_in[3];
    const float* b_hh  = (const float*)d_in[4];
    const float* w_lin = (const float*)d_in[5];
    const float* b_lin = (const float*)d_in[6];

    float* out = (float*)d_out;
    const int BT = in_sizes[0];          // B * T
    const int T  = BT / BATCH;
    float* states = out + BT;            // d_out = [out | states]

    gru_kernel<<<BATCH / 2, 256>>>(x, w_ih, w_hh, b_ih, b_hh, states, T);
    head_kernel<<<BT / HROWS, 128>>>(states, x, w_lin, b_lin, out, BT);
}